// round 3
// baseline (speedup 1.0000x reference)
#include <cuda_runtime.h>
#include <math.h>

#define N_G   1024
#define NS    (N_G * 25)
#define SCALE 1.0f
#define DXC   (2.0f / 31.0f)
#define QCUT  60.0f                // dropped terms < e^-30 of dominant: negligible
#define GPB   16                   // gaussians per block
#define CANDCAP 352

__device__ __forceinline__ float tanha(float x) {
    float y;
    asm("tanh.approx.f32 %0, %1;" : "=f"(y) : "f"(x));
    return y;
}

// dynamic smem layout (float offsets)
#define OFF_SWC   0        // 50*75
#define OFF_SWE   3750     // 180
#define OFF_SWL   3930     // 80*80
#define OFF_SBC   10330    // 50
#define OFF_SBE   10380    // 30
#define OFF_SBL   10410    // 80
#define OFF_SHW   10490    // 160
#define OFF_SHB   10650    // 2
#define OFF_SPRM  10652    // 16*9
#define OFF_IMGT  10796    // 75*20  imgT[kk][g]
#define OFF_SHT   12296    // 80*20
#define OFF_SH2T  13896    // 80*20
#define OFF_CA    15496    // 352*4 (float4)
#define OFF_CB    16904    // 352*4 (float4)
#define OFF_MISC  18312    // wcnt8, wbase8, total1
#define SMEM_FLTS 18336

__global__ void __launch_bounds__(256) k_fused(
    const float* __restrict__ means,  const float* __restrict__ u,
    const float* __restrict__ scaling,const float* __restrict__ transform,
    const float* __restrict__ conv_w, const float* __restrict__ conv_b,
    const float* __restrict__ emb_w,  const float* __restrict__ emb_b,
    const float* __restrict__ lin1_w, const float* __restrict__ lin1_b,
    const float* __restrict__ sol_w,  const float* __restrict__ sol_b,
    const float* __restrict__ tr_w,   const float* __restrict__ tr_b,
    const float* __restrict__ sc_w,   const float* __restrict__ sc_b,
    const float* __restrict__ tf_w,   const float* __restrict__ tf_b,
    float* __restrict__ out)
{
    extern __shared__ float sm[];
    float* swc  = sm + OFF_SWC;
    float* swe  = sm + OFF_SWE;
    float* swl  = sm + OFF_SWL;
    float* sbc  = sm + OFF_SBC;
    float* sbe  = sm + OFF_SBE;
    float* sbl  = sm + OFF_SBL;
    float* shw  = sm + OFF_SHW;
    float* shb  = sm + OFF_SHB;
    float* sprm = sm + OFF_SPRM;
    float* imgT = sm + OFF_IMGT;
    float* shT  = sm + OFF_SHT;
    float* sh2T = sm + OFF_SH2T;
    float4* cA  = (float4*)(sm + OFF_CA);
    float4* cB  = (float4*)(sm + OFF_CB);
    int*   s_wcnt  = (int*)(sm + OFF_MISC);
    int*   s_wbase = (int*)(sm + OFF_MISC + 8);
    int*   s_total = (int*)(sm + OFF_MISC + 16);

    const int m   = blockIdx.x;         // network 0..3
    const int g0  = blockIdx.y * GPB;   // first gaussian of group
    const int tid = threadIdx.x;
    const int od  = (m == 1 || m == 2) ? 2 : 1;

    // ---------------- phase 1: load weights + params ----------------
    for (int idx = tid; idx < 3750; idx += 256) swc[idx] = conv_w[m * 3750 + idx];
    for (int idx = tid; idx < 180;  idx += 256) swe[idx] = emb_w[m * 180 + idx];
    for (int idx = tid; idx < 6400; idx += 256) swl[idx] = lin1_w[m * 6400 + idx];
    if (tid < 50) sbc[tid] = conv_b[m * 50 + tid];
    if (tid >= 64 && tid < 94)  sbe[tid - 64] = emb_b[m * 30 + (tid - 64)];
    if (tid >= 96 && tid < 176) sbl[tid - 96] = lin1_b[m * 80 + (tid - 96)];
    const float* hw; const float* hb;
    if      (m == 0) { hw = sol_w; hb = sol_b; }
    else if (m == 1) { hw = tr_w;  hb = tr_b;  }
    else if (m == 2) { hw = sc_w;  hb = sc_b;  }
    else             { hw = tf_w;  hb = tf_b;  }
    for (int idx = tid; idx < 80 * od; idx += 256) shw[idx] = hw[idx];
    if (tid < od) shb[tid] = hb[tid];
    if (tid >= 224 && tid < 224 + GPB) {
        int g = tid - 224, i = g0 + g;
        sprm[g * 9 + 0] = means[2 * i];
        sprm[g * 9 + 1] = means[2 * i + 1];
        sprm[g * 9 + 2] = u[i];
        sprm[g * 9 + 3] = scaling[2 * i];
        sprm[g * 9 + 4] = scaling[2 * i + 1];
        sprm[g * 9 + 5] = transform[i];
    }
    if (tid == 0) *s_total = 0;
    __syncthreads();

    // ---------------- phase 2: bbox (each thread, redundant) ----------------
    float bminx = 1e30f, bmaxx = -1e30f, bminy = 1e30f, bmaxy = -1e30f;
    #pragma unroll
    for (int g = 0; g < GPB; ++g) {
        float mx = sprm[g * 9 + 0], my = sprm[g * 9 + 1];
        bminx = fminf(bminx, mx); bmaxx = fmaxf(bmaxx, mx);
        bminy = fminf(bminy, my); bmaxy = fmaxf(bmaxy, my);
    }
    bminx -= 2.0f * DXC; bmaxx += 2.0f * DXC;
    bminy -= 2.0f * DXC; bmaxy += 2.0f * DXC;

    // ---------------- phase 3: candidate scan + compaction ----------------
    const int wid = tid >> 5, lane = tid & 31;
    for (int c = 0; c < N_G / 256; ++c) {
        int j = c * 256 + tid;
        float mx = means[2 * j], my = means[2 * j + 1];
        float s0 = scaling[2 * j], s1 = scaling[2 * j + 1], t = transform[j];
        float A = s0 * s0, B = s0 * t, C = t * t + s1 * s1;
        float inv = 1.0f / (A * C - B * B);
        float ca =  C * inv, cb = -B * inv, cc = A * inv;
        float h = 0.5f * (A + C);
        float r = sqrtf(0.25f * (A - C) * (A - C) + B * B);
        float r2max = QCUT * (h + r);
        float ddx = fmaxf(fmaxf(bminx - mx, mx - bmaxx), 0.0f);
        float ddy = fmaxf(fmaxf(bminy - my, my - bmaxy), 0.0f);
        bool pred = (ddx * ddx + ddy * ddy) <= r2max;
        unsigned bm = __ballot_sync(0xffffffffu, pred);
        if (lane == 0) s_wcnt[wid] = __popc(bm);
        __syncthreads();
        if (tid == 0) {
            int acc = *s_total;
            for (int w2 = 0; w2 < 8; ++w2) { s_wbase[w2] = acc; acc += s_wcnt[w2]; }
            *s_total = acc;
        }
        __syncthreads();
        if (pred) {
            int idx = s_wbase[wid] + __popc(bm & ((1u << lane) - 1u));
            if (idx < CANDCAP) {
                cA[idx] = make_float4(mx, my, r2max, u[j]);
                cB[idx] = make_float4(ca, cb, cc, ca + cc);
            }
        }
        __syncthreads();
    }
    int cnt = *s_total;
    if (cnt > CANDCAP) cnt = CANDCAP;

    // ---------------- phase 4: sample evaluation (400 tasks) ----------------
    for (int t = tid; t < GPB * 25; t += 256) {
        int g  = t / 25;
        int k  = t % 25;
        int kx = k / 5, ky = k % 5;
        float sx = sprm[g * 9 + 0] + (float)(kx - 2) * DXC;
        float sy = sprm[g * 9 + 1] + (float)(ky - 2) * DXC;
        float us = 0.0f, pd = 0.0f;
        for (int t2 = 0; t2 < cnt; ++t2) {
            float4 A = cA[t2];
            float dx = sx - A.x;
            float dy = sy - A.y;
            float d2 = dx * dx + dy * dy;
            if (d2 <= A.z) {
                float4 Bv = cB[t2];
                float Cd0 = Bv.x * dx + Bv.y * dy;
                float Cd1 = Bv.y * dx + Bv.z * dy;
                float q   = dx * Cd0 + dy * Cd1;
                float w   = __expf(-0.5f * q) * A.w;
                us += w;
                pd += w * (Cd0 * Cd0 + Cd1 * Cd1 - Bv.w);
            }
        }
        float maskv = (fabsf(sx) < SCALE && fabsf(sy) < SCALE) ? 1.0f : 0.0f;
        imgT[( 0 + k) * 20 + g] = us;
        imgT[(25 + k) * 20 + g] = pd;
        imgT[(50 + k) * 20 + g] = maskv;
    }
    __syncthreads();

    // ---------------- phase 5: conv (tid<100) + embedding (128<=tid<248) ----
    if (tid < 100) {
        int o  = tid >> 1;
        int gb = (tid & 1) * 8;
        float b0 = sbc[o];
        float acc[8] = {b0, b0, b0, b0, b0, b0, b0, b0};
        const float* wr = &swc[o * 75];
        for (int kk = 0; kk < 75; ++kk) {
            float w = wr[kk];
            float4 v0 = *(const float4*)&imgT[kk * 20 + gb];
            float4 v1 = *(const float4*)&imgT[kk * 20 + gb + 4];
            acc[0] = fmaf(w, v0.x, acc[0]); acc[1] = fmaf(w, v0.y, acc[1]);
            acc[2] = fmaf(w, v0.z, acc[2]); acc[3] = fmaf(w, v0.w, acc[3]);
            acc[4] = fmaf(w, v1.x, acc[4]); acc[5] = fmaf(w, v1.y, acc[5]);
            acc[6] = fmaf(w, v1.z, acc[6]); acc[7] = fmaf(w, v1.w, acc[7]);
        }
        #pragma unroll
        for (int b = 0; b < 8; ++b) shT[o * 20 + gb + b] = tanha(acc[b]);
    } else if (tid >= 128 && tid < 248) {
        int et = tid - 128;
        int q  = et >> 2;           // 0..29
        int gb = (et & 3) * 4;
        float be = sbe[q];
        float acc[4] = {be, be, be, be};
        #pragma unroll
        for (int p = 0; p < 6; ++p) {
            float w = swe[p * 30 + q];
            acc[0] = fmaf(sprm[(gb + 0) * 9 + p], w, acc[0]);
            acc[1] = fmaf(sprm[(gb + 1) * 9 + p], w, acc[1]);
            acc[2] = fmaf(sprm[(gb + 2) * 9 + p], w, acc[2]);
            acc[3] = fmaf(sprm[(gb + 3) * 9 + p], w, acc[3]);
        }
        #pragma unroll
        for (int b = 0; b < 4; ++b) shT[(50 + q) * 20 + gb + b] = tanha(acc[b]);
    }
    __syncthreads();

    // ---------------- phase 6: 80x80 (2q x 4g tiles, 160 tasks) ----------------
    if (tid < 160) {
        int q0 = (tid >> 2) * 2;    // 0..78 step 2
        int gb = (tid & 3) * 4;
        float acc0[4], acc1[4];
        float bl0 = sbl[q0], bl1 = sbl[q0 + 1];
        #pragma unroll
        for (int b = 0; b < 4; ++b) { acc0[b] = bl0; acc1[b] = bl1; }
        for (int p = 0; p < 80; ++p) {
            float2 wv = *(const float2*)&swl[p * 80 + q0];
            float4 hv = *(const float4*)&shT[p * 20 + gb];
            acc0[0] = fmaf(wv.x, hv.x, acc0[0]); acc0[1] = fmaf(wv.x, hv.y, acc0[1]);
            acc0[2] = fmaf(wv.x, hv.z, acc0[2]); acc0[3] = fmaf(wv.x, hv.w, acc0[3]);
            acc1[0] = fmaf(wv.y, hv.x, acc1[0]); acc1[1] = fmaf(wv.y, hv.y, acc1[1]);
            acc1[2] = fmaf(wv.y, hv.z, acc1[2]); acc1[3] = fmaf(wv.y, hv.w, acc1[3]);
        }
        #pragma unroll
        for (int b = 0; b < 4; ++b) {
            sh2T[q0 * 20 + gb + b]       = tanha(acc0[b]);
            sh2T[(q0 + 1) * 20 + gb + b] = tanha(acc1[b]);
        }
    }
    __syncthreads();

    // ---------------- phase 7: head + residual update ----------------
    if (tid < GPB * od) {
        int g = tid & (GPB - 1);
        int d = tid >> 4;
        float acc = shb[d];
        for (int p = 0; p < 80; ++p)
            acc = fmaf(sh2T[p * 20 + g], shw[p * od + d], acc);
        int i = g0 + g;
        if      (m == 0) out[i * 6 + 0]     = sprm[g * 9 + 2]     + acc;
        else if (m == 1) out[i * 6 + 1 + d] = sprm[g * 9 + d]     + acc;
        else if (m == 2) out[i * 6 + 3 + d] = sprm[g * 9 + 3 + d] * __expf(acc);
        else             out[i * 6 + 5]     = sprm[g * 9 + 5]     + acc;
    }
}

// ---------------------------------------------------------------------------
extern "C" void kernel_launch(void* const* d_in, const int* in_sizes, int n_in,
                              void* d_out, int out_size)
{
    const float* means     = (const float*)d_in[0];
    const float* u         = (const float*)d_in[1];
    const float* scaling   = (const float*)d_in[2];
    const float* transform = (const float*)d_in[3];
    const float* conv_w    = (const float*)d_in[4];
    const float* conv_b    = (const float*)d_in[5];
    const float* emb_w     = (const float*)d_in[6];
    const float* emb_b     = (const float*)d_in[7];
    const float* lin1_w    = (const float*)d_in[8];
    const float* lin1_b    = (const float*)d_in[9];
    const float* sol_w     = (const float*)d_in[10];
    const float* sol_b     = (const float*)d_in[11];
    const float* tr_w      = (const float*)d_in[12];
    const float* tr_b      = (const float*)d_in[13];
    const float* sc_w      = (const float*)d_in[14];
    const float* sc_b      = (const float*)d_in[15];
    const float* tf_w      = (const float*)d_in[16];
    const float* tf_b      = (const float*)d_in[17];
    float* out             = (float*)d_out;

    static int smem_set = 0;
    if (!smem_set) {
        cudaFuncSetAttribute(k_fused, cudaFuncAttributeMaxDynamicSharedMemorySize,
                             SMEM_FLTS * (int)sizeof(float));
        smem_set = 1;
    }

    dim3 grid(4, N_G / GPB, 1);
    k_fused<<<grid, 256, SMEM_FLTS * sizeof(float)>>>(
        means, u, scaling, transform,
        conv_w, conv_b, emb_w, emb_b, lin1_w, lin1_b,
        sol_w, sol_b, tr_w, tr_b, sc_w, sc_b, tf_w, tf_b, out);
}

// round 4
// speedup vs baseline: 1.2281x; 1.2281x over previous
#include <cuda_runtime.h>
#include <math.h>

#define N_G   1024
#define SCALE 1.0f
#define DXC   (2.0f / 31.0f)
#define QCUT  60.0f                // dropped terms < e^-30 of dominant: negligible
#define GPB   8                    // gaussians per block in net kernel
#define CANDCAP 640

__device__ float d_img[N_G * 75];  // (N, 3, 5, 5): c*25 + kx*5 + ky

__device__ __forceinline__ float tanha(float x) {
    float y;
    asm("tanh.approx.f32 %0, %1;" : "=f"(y) : "f"(x));
    return y;
}

// ---------------------------------------------------------------------------
// Kernel 1: sampling with per-block candidate list.
// 100 blocks x 256 threads; block = 256 consecutive samples (~10 gaussians).
// ---------------------------------------------------------------------------
__global__ void __launch_bounds__(256) k_samples(
    const float* __restrict__ means, const float* __restrict__ u,
    const float* __restrict__ scaling, const float* __restrict__ transform)
{
    __shared__ float4 cA[CANDCAP];   // mx, my, r2max, u
    __shared__ float4 cB[CANDCAP];   // a, b, c, trace
    __shared__ int    s_wcnt[8], s_wbase[8], s_total;
    __shared__ float  s_bb[4];
    __shared__ float  s_red[8][4];

    const int tid = threadIdx.x;
    if (tid == 0) s_total = 0;

    // this thread's sample position
    const int s  = blockIdx.x * 256 + tid;
    const int i  = s / 25;
    const int k  = s % 25;
    const int kx = k / 5;
    const int ky = k % 5;
    const float sx = means[2 * i]     + (float)(kx - 2) * DXC;
    const float sy = means[2 * i + 1] + (float)(ky - 2) * DXC;

    // block bbox of sample positions
    float mnx = sx, mxx = sx, mny = sy, mxy = sy;
    #pragma unroll
    for (int o = 16; o > 0; o >>= 1) {
        mnx = fminf(mnx, __shfl_xor_sync(0xffffffffu, mnx, o));
        mxx = fmaxf(mxx, __shfl_xor_sync(0xffffffffu, mxx, o));
        mny = fminf(mny, __shfl_xor_sync(0xffffffffu, mny, o));
        mxy = fmaxf(mxy, __shfl_xor_sync(0xffffffffu, mxy, o));
    }
    if ((tid & 31) == 0) {
        s_red[tid >> 5][0] = mnx; s_red[tid >> 5][1] = mxx;
        s_red[tid >> 5][2] = mny; s_red[tid >> 5][3] = mxy;
    }
    __syncthreads();
    if (tid == 0) {
        float a0 = s_red[0][0], a1 = s_red[0][1], a2 = s_red[0][2], a3 = s_red[0][3];
        for (int w2 = 1; w2 < 8; ++w2) {
            a0 = fminf(a0, s_red[w2][0]); a1 = fmaxf(a1, s_red[w2][1]);
            a2 = fminf(a2, s_red[w2][2]); a3 = fmaxf(a3, s_red[w2][3]);
        }
        s_bb[0] = a0; s_bb[1] = a1; s_bb[2] = a2; s_bb[3] = a3;
    }
    __syncthreads();
    const float bminx = s_bb[0], bmaxx = s_bb[1], bminy = s_bb[2], bmaxy = s_bb[3];

    // candidate scan + deterministic compaction (conics computed inline)
    const int wid = tid >> 5, lane = tid & 31;
    for (int c = 0; c < N_G / 256; ++c) {
        int j = c * 256 + tid;
        float mx = means[2 * j], my = means[2 * j + 1];
        float s0 = scaling[2 * j], s1 = scaling[2 * j + 1], t = transform[j];
        float A = s0 * s0, B = s0 * t, C = t * t + s1 * s1;
        float inv = 1.0f / (A * C - B * B);
        float ca =  C * inv, cb = -B * inv, cc = A * inv;
        float h = 0.5f * (A + C);
        float r = sqrtf(0.25f * (A - C) * (A - C) + B * B);
        float r2max = QCUT * (h + r);
        float ddx = fmaxf(fmaxf(bminx - mx, mx - bmaxx), 0.0f);
        float ddy = fmaxf(fmaxf(bminy - my, my - bmaxy), 0.0f);
        bool pred = (ddx * ddx + ddy * ddy) <= r2max;
        unsigned bm = __ballot_sync(0xffffffffu, pred);
        if (lane == 0) s_wcnt[wid] = __popc(bm);
        __syncthreads();
        if (tid == 0) {
            int acc = s_total;
            for (int w2 = 0; w2 < 8; ++w2) { s_wbase[w2] = acc; acc += s_wcnt[w2]; }
            s_total = acc;
        }
        __syncthreads();
        if (pred) {
            int idx = s_wbase[wid] + __popc(bm & ((1u << lane) - 1u));
            if (idx < CANDCAP) {
                cA[idx] = make_float4(mx, my, r2max, u[j]);
                cB[idx] = make_float4(ca, cb, cc, ca + cc);
            }
        }
        __syncthreads();
    }
    int cnt = s_total;
    if (cnt > CANDCAP) cnt = CANDCAP;

    // branchless evaluation over candidates
    float us = 0.0f, pd = 0.0f;
    for (int t2 = 0; t2 < cnt; ++t2) {
        float4 A  = cA[t2];
        float4 Bv = cB[t2];
        float dx = sx - A.x;
        float dy = sy - A.y;
        float Cd0 = Bv.x * dx + Bv.y * dy;
        float Cd1 = Bv.y * dx + Bv.z * dy;
        float q   = dx * Cd0 + dy * Cd1;
        float w   = __expf(-0.5f * q) * A.w;
        us += w;
        pd += w * (Cd0 * Cd0 + Cd1 * Cd1 - Bv.w);
    }
    float maskv = (fabsf(sx) < SCALE && fabsf(sy) < SCALE) ? 1.0f : 0.0f;
    d_img[i * 75 +  0 + k] = us;
    d_img[i * 75 + 25 + k] = pd;
    d_img[i * 75 + 50 + k] = maskv;
}

// ---------------------------------------------------------------------------
// Kernel 2: 4 stacked networks. GPB=8, grid (4, 128) = 512 blocks, 160 threads.
// smem ~57KB -> ~3.5 blocks/SM resident, all threads active in heavy phases.
// ---------------------------------------------------------------------------
#define IST 16   // imgT stride
#define HST 14   // shT/sh2T stride

#define OFF_SWC   0                       // 50*75
#define OFF_SWE   3750                    // 180
#define OFF_SWL   3930                    // 80*80
#define OFF_SBC   10330                   // 50
#define OFF_SBE   10380                   // 30
#define OFF_SBL   10410                   // 80
#define OFF_SHW   10490                   // 160
#define OFF_SHB   10650                   // 2
#define OFF_SPRM  10652                   // 8*9 = 72
#define OFF_IMGT  10724                   // 75*16 = 1200
#define OFF_SHT   11924                   // 80*14 = 1120
#define OFF_SH2T  13044                   // 80*14 = 1120
#define SMEM_FLTS 14164

__global__ void __launch_bounds__(160) k_net(
    const float* __restrict__ conv_w, const float* __restrict__ conv_b,
    const float* __restrict__ emb_w,  const float* __restrict__ emb_b,
    const float* __restrict__ lin1_w, const float* __restrict__ lin1_b,
    const float* __restrict__ sol_w,  const float* __restrict__ sol_b,
    const float* __restrict__ tr_w,   const float* __restrict__ tr_b,
    const float* __restrict__ sc_w,   const float* __restrict__ sc_b,
    const float* __restrict__ tf_w,   const float* __restrict__ tf_b,
    const float* __restrict__ means,  const float* __restrict__ u,
    const float* __restrict__ scaling,const float* __restrict__ transform,
    float* __restrict__ out)
{
    extern __shared__ float sm[];
    float* swc  = sm + OFF_SWC;
    float* swe  = sm + OFF_SWE;
    float* swl  = sm + OFF_SWL;
    float* sbc  = sm + OFF_SBC;
    float* sbe  = sm + OFF_SBE;
    float* sbl  = sm + OFF_SBL;
    float* shw  = sm + OFF_SHW;
    float* shb  = sm + OFF_SHB;
    float* sprm = sm + OFF_SPRM;
    float* imgT = sm + OFF_IMGT;
    float* shT  = sm + OFF_SHT;
    float* sh2T = sm + OFF_SH2T;

    const int m   = blockIdx.x;
    const int g0  = blockIdx.y * GPB;
    const int tid = threadIdx.x;
    const int od  = (m == 1 || m == 2) ? 2 : 1;

    // ---- loads ----
    for (int idx = tid; idx < 3750; idx += 160) swc[idx] = conv_w[m * 3750 + idx];
    for (int idx = tid; idx < 180;  idx += 160) swe[idx] = emb_w[m * 180 + idx];
    for (int idx = tid; idx < 6400; idx += 160) swl[idx] = lin1_w[m * 6400 + idx];
    if (tid < 50) sbc[tid] = conv_b[m * 50 + tid];
    if (tid >= 64 && tid < 94)  sbe[tid - 64] = emb_b[m * 30 + (tid - 64)];
    if (tid >= 64 && tid < 144) sbl[tid - 64] = lin1_b[m * 80 + (tid - 64)];
    const float* hw; const float* hb;
    if      (m == 0) { hw = sol_w; hb = sol_b; }
    else if (m == 1) { hw = tr_w;  hb = tr_b;  }
    else if (m == 2) { hw = sc_w;  hb = sc_b;  }
    else             { hw = tf_w;  hb = tf_b;  }
    for (int idx = tid; idx < 80 * od; idx += 160) shw[idx] = hw[idx];
    if (tid < od) shb[tid] = hb[tid];
    if (tid >= 144 && tid < 144 + GPB) {
        int g = tid - 144, i = g0 + g;
        sprm[g * 9 + 0] = means[2 * i];
        sprm[g * 9 + 1] = means[2 * i + 1];
        sprm[g * 9 + 2] = u[i];
        sprm[g * 9 + 3] = scaling[2 * i];
        sprm[g * 9 + 4] = scaling[2 * i + 1];
        sprm[g * 9 + 5] = transform[i];
    }
    for (int idx = tid; idx < GPB * 75; idx += 160) {
        int g = idx / 75, kk = idx - g * 75;
        imgT[kk * IST + g] = d_img[(g0 + g) * 75 + kk];
    }
    __syncthreads();

    // ---- stage 1: conv (tid<100: o=tid>>1, 4g) + emb (tid 100..159) ----
    if (tid < 100) {
        int o  = tid >> 1;
        int gb = (tid & 1) * 4;
        float b0 = sbc[o];
        float acc[4] = {b0, b0, b0, b0};
        const float* wr = &swc[o * 75];
        #pragma unroll 5
        for (int kk = 0; kk < 75; ++kk) {
            float w = wr[kk];
            float4 v = *(const float4*)&imgT[kk * IST + gb];
            acc[0] = fmaf(w, v.x, acc[0]); acc[1] = fmaf(w, v.y, acc[1]);
            acc[2] = fmaf(w, v.z, acc[2]); acc[3] = fmaf(w, v.w, acc[3]);
        }
        #pragma unroll
        for (int b = 0; b < 4; ++b) shT[o * HST + gb + b] = tanha(acc[b]);
    } else {
        int et = tid - 100;           // 0..59
        int q  = et >> 1;             // 0..29
        int gb = (et & 1) * 4;
        float be = sbe[q];
        float acc[4] = {be, be, be, be};
        #pragma unroll
        for (int p = 0; p < 6; ++p) {
            float w = swe[p * 30 + q];
            acc[0] = fmaf(sprm[(gb + 0) * 9 + p], w, acc[0]);
            acc[1] = fmaf(sprm[(gb + 1) * 9 + p], w, acc[1]);
            acc[2] = fmaf(sprm[(gb + 2) * 9 + p], w, acc[2]);
            acc[3] = fmaf(sprm[(gb + 3) * 9 + p], w, acc[3]);
        }
        #pragma unroll
        for (int b = 0; b < 4; ++b) shT[(50 + q) * HST + gb + b] = tanha(acc[b]);
    }
    __syncthreads();

    // ---- stage 2: 80x80, 2q x 2g tiles = exactly 160 tasks ----
    {
        int q0 = (tid >> 2) * 2;      // 0..78
        int gb = (tid & 3) * 2;       // 0,2,4,6
        float acc00 = sbl[q0],     acc01 = sbl[q0];
        float acc10 = sbl[q0 + 1], acc11 = sbl[q0 + 1];
        #pragma unroll 4
        for (int p = 0; p < 80; ++p) {
            float2 wv = *(const float2*)&swl[p * 80 + q0];
            float2 hv = *(const float2*)&shT[p * HST + gb];
            acc00 = fmaf(wv.x, hv.x, acc00); acc01 = fmaf(wv.x, hv.y, acc01);
            acc10 = fmaf(wv.y, hv.x, acc10); acc11 = fmaf(wv.y, hv.y, acc11);
        }
        sh2T[q0 * HST + gb]           = tanha(acc00);
        sh2T[q0 * HST + gb + 1]       = tanha(acc01);
        sh2T[(q0 + 1) * HST + gb]     = tanha(acc10);
        sh2T[(q0 + 1) * HST + gb + 1] = tanha(acc11);
    }
    __syncthreads();

    // ---- stage 3: head + residual update ----
    if (tid < GPB * od) {
        int g = tid & (GPB - 1);
        int d = tid >> 3;
        float acc = shb[d];
        #pragma unroll 8
        for (int p = 0; p < 80; ++p)
            acc = fmaf(sh2T[p * HST + g], shw[p * od + d], acc);
        int i = g0 + g;
        if      (m == 0) out[i * 6 + 0]     = sprm[g * 9 + 2]     + acc;
        else if (m == 1) out[i * 6 + 1 + d] = sprm[g * 9 + d]     + acc;
        else if (m == 2) out[i * 6 + 3 + d] = sprm[g * 9 + 3 + d] * __expf(acc);
        else             out[i * 6 + 5]     = sprm[g * 9 + 5]     + acc;
    }
}

// ---------------------------------------------------------------------------
extern "C" void kernel_launch(void* const* d_in, const int* in_sizes, int n_in,
                              void* d_out, int out_size)
{
    const float* means     = (const float*)d_in[0];
    const float* u         = (const float*)d_in[1];
    const float* scaling   = (const float*)d_in[2];
    const float* transform = (const float*)d_in[3];
    const float* conv_w    = (const float*)d_in[4];
    const float* conv_b    = (const float*)d_in[5];
    const float* emb_w     = (const float*)d_in[6];
    const float* emb_b     = (const float*)d_in[7];
    const float* lin1_w    = (const float*)d_in[8];
    const float* lin1_b    = (const float*)d_in[9];
    const float* sol_w     = (const float*)d_in[10];
    const float* sol_b     = (const float*)d_in[11];
    const float* tr_w      = (const float*)d_in[12];
    const float* tr_b      = (const float*)d_in[13];
    const float* sc_w      = (const float*)d_in[14];
    const float* sc_b      = (const float*)d_in[15];
    const float* tf_w      = (const float*)d_in[16];
    const float* tf_b      = (const float*)d_in[17];
    float* out             = (float*)d_out;

    static int smem_set = 0;
    if (!smem_set) {
        cudaFuncSetAttribute(k_net, cudaFuncAttributeMaxDynamicSharedMemorySize,
                             SMEM_FLTS * (int)sizeof(float));
        smem_set = 1;
    }

    k_samples<<<N_G * 25 / 256, 256>>>(means, u, scaling, transform);
    dim3 grid(4, N_G / GPB, 1);
    k_net<<<grid, 160, SMEM_FLTS * sizeof(float)>>>(
        conv_w, conv_b, emb_w, emb_b, lin1_w, lin1_b,
        sol_w, sol_b, tr_w, tr_b, sc_w, sc_b, tf_w, tf_b,
        means, u, scaling, transform, out);
}